// round 10
// baseline (speedup 1.0000x reference)
#include <cuda_runtime.h>
#include <cuda_bf16.h>
#include <cstdint>

// ---------------------------------------------------------------------------
// 2-layer GRU (H=32, INPUT=4, B=4096, S=512) + FC(32->32) + FC(32->1)
//
// SINGLE fused kernel. One warp per batch row, lane per hidden unit.
// Per 64-step chunk: phase 1 runs GRU layer 1 (h1 -> smem buffer), phase 2
// runs GRU layer 2 over the same chunk. The two phases share one register
// weight array W[96], reloaded from gmem (L1-hot) at each phase start, so
// the register high-water is one layer's weights, not two.
// All hot-loop smem reads are broadcast (no crossbar pressure — R9 lesson).
// Math ordering identical to R6 (rel_err 1.1e-6).
// ---------------------------------------------------------------------------

#define B_ROWS 4096
#define SEQ    512
#define HID    32
#define CHUNK  64
#define NCHUNK (SEQ / CHUNK)

typedef unsigned long long ull;

__device__ __forceinline__ ull ffma2(ull a, ull b, ull c) {
    ull d;
    asm("fma.rn.f32x2 %0, %1, %2, %3;" : "=l"(d) : "l"(a), "l"(b), "l"(c));
    return d;
}
__device__ __forceinline__ float hsum2(ull v) {
    float2 r;
    asm("mov.b64 {%0, %1}, %2;" : "=f"(r.x), "=f"(r.y) : "l"(v));
    return r.x + r.y;
}
__device__ __forceinline__ float tanh_ap(float x) {
    float y;
    asm("tanh.approx.f32 %0, %1;" : "=f"(y) : "f"(x));
    return y;
}
__device__ __forceinline__ float sig_ap(float x) {
    return fmaf(0.5f, tanh_ap(0.5f * x), 0.5f);
}
__device__ __forceinline__ void cp_async16(uint32_t smem_addr, const float* gptr) {
    asm volatile("cp.async.ca.shared.global [%0], [%1], 16;"
                 :: "r"(smem_addr), "l"(gptr));
}
__device__ __forceinline__ void cp_commit() {
    asm volatile("cp.async.commit_group;");
}
__device__ __forceinline__ void cp_wait_all() {
    asm volatile("cp.async.wait_group 0;");
}
__device__ __forceinline__ void cp_wait_1() {
    asm volatile("cp.async.wait_group 1;");
}

__global__ __launch_bounds__(128, 2)
void gru_fused_kernel(const float* __restrict__ x,
                      const float* __restrict__ Wih0,  // [96,4]
                      const float* __restrict__ Whh0,  // [96,32]
                      const float* __restrict__ bih0,  // [96]
                      const float* __restrict__ bhh0,  // [96]
                      const float* __restrict__ Wih1,  // [96,32]
                      const float* __restrict__ Whh1,  // [96,32]
                      const float* __restrict__ bih1,  // [96]
                      const float* __restrict__ bhh1,  // [96]
                      const float* __restrict__ Wfc2,  // [32,32]
                      const float* __restrict__ bfc2,  // [32]
                      const float* __restrict__ Wfc,   // [1,32]
                      const float* __restrict__ bfc,   // [1]
                      float* __restrict__ out)
{
    __shared__ __align__(16) float hbuf[4][2][HID];            // 1 KB
    __shared__ __align__(16) float xbuf[4][2][CHUNK][4];       // 8 KB
    __shared__ __align__(16) float h1buf[4][CHUNK][HID];       // 32 KB

    const int warp = (blockIdx.x * blockDim.x + threadIdx.x) >> 5;
    const int wl   = threadIdx.x >> 5;
    const int lane = threadIdx.x & 31;

    // Biases (persist, 8 regs)
    const float br0  = bih0[lane]      + bhh0[lane];
    const float bz0  = bih0[32 + lane] + bhh0[32 + lane];
    const float bin0 = bih0[64 + lane];
    const float bhn0 = bhh0[64 + lane];
    const float br1  = bih1[lane]      + bhh1[lane];
    const float bz1  = bih1[32 + lane] + bhh1[32 + lane];
    const float bin1 = bih1[64 + lane];
    const float bhn1 = bhh1[64 + lane];

    const float* xsrc = x + (size_t)warp * SEQ * 4;

    const uint32_t xb0 = (uint32_t)__cvta_generic_to_shared(&xbuf[wl][0][0][0]);
    const uint32_t xb1 = (uint32_t)__cvta_generic_to_shared(&xbuf[wl][1][0][0]);

    // Prefetch x chunk 0 (1 KB = 2 x 16B per lane)
    cp_async16(xb0 + lane * 16,       xsrc + lane * 4);
    cp_async16(xb0 + 512 + lane * 16, xsrc + 128 + lane * 4);
    cp_commit();

    // Phase-shared register weight array (constant-indexed -> registers)
    ull W[96];

    float h1s = 0.0f;   // layer-1 hidden state (this lane's unit)
    float h2s = 0.0f;   // layer-2 hidden state

#pragma unroll 1
    for (int c = 0; c < NCHUNK; c++) {
        // =================== PHASE 1: layer 1, steps [c*64, c*64+64) =======
        // Load layer-1 recurrent weights: W[0..15]=r, [16..31]=z, [32..47]=n
        {
            const ull* pr = reinterpret_cast<const ull*>(Whh0 + (lane)      * HID);
            const ull* pz = reinterpret_cast<const ull*>(Whh0 + (32 + lane) * HID);
            const ull* pn = reinterpret_cast<const ull*>(Whh0 + (64 + lane) * HID);
#pragma unroll
            for (int k = 0; k < 16; k++) {
                W[k] = pr[k]; W[16 + k] = pz[k]; W[32 + k] = pn[k];
            }
        }
        const float4 wir = reinterpret_cast<const float4*>(Wih0)[lane];
        const float4 wiz = reinterpret_cast<const float4*>(Wih0)[32 + lane];
        const float4 win = reinterpret_cast<const float4*>(Wih0)[64 + lane];

        // Wait for this chunk's x, then prefetch next chunk's x.
        if (c + 1 < NCHUNK) {
            cp_wait_1();          // previous prefetch (this chunk) may still fly
        } else {
            cp_wait_all();
        }
        __syncwarp();
        if (c + 1 < NCHUNK) {
            const uint32_t xb = (c & 1) ? xb0 : xb1;
            const float* g = xsrc + (c + 1) * CHUNK * 4;
            cp_async16(xb + lane * 16,       g + lane * 4);
            cp_async16(xb + 512 + lane * 16, g + 128 + lane * 4);
            cp_commit();
        }
        cp_wait_1();   // ensure THIS chunk's buffer (now oldest-1) is ready
        __syncwarp();

        const float4* xchunk =
            reinterpret_cast<const float4*>(&xbuf[wl][c & 1][0][0]);

#pragma unroll 2
        for (int t = 0; t < CHUNK; t++) {
            hbuf[wl][t & 1][lane] = h1s;
            __syncwarp();
            const float4 xv = xchunk[t];
            const ulonglong2* hp =
                reinterpret_cast<const ulonglong2*>(&hbuf[wl][t & 1][0]);

            float ar = br0, az = bz0, xn = bin0;
            ar = fmaf(wir.x, xv.x, ar); ar = fmaf(wir.y, xv.y, ar);
            ar = fmaf(wir.z, xv.z, ar); ar = fmaf(wir.w, xv.w, ar);
            az = fmaf(wiz.x, xv.x, az); az = fmaf(wiz.y, xv.y, az);
            az = fmaf(wiz.z, xv.z, az); az = fmaf(wiz.w, xv.w, az);
            xn = fmaf(win.x, xv.x, xn); xn = fmaf(win.y, xv.y, xn);
            xn = fmaf(win.z, xv.z, xn); xn = fmaf(win.w, xv.w, xn);

            ull accr = 0ull, accz = 0ull, accn = 0ull;
#pragma unroll
            for (int k = 0; k < 8; k++) {
                const ulonglong2 hv = hp[k];
                accr = ffma2(W[2 * k],          hv.x, accr);
                accz = ffma2(W[16 + 2 * k],     hv.x, accz);
                accn = ffma2(W[32 + 2 * k],     hv.x, accn);
                accr = ffma2(W[2 * k + 1],      hv.y, accr);
                accz = ffma2(W[16 + 2 * k + 1], hv.y, accz);
                accn = ffma2(W[32 + 2 * k + 1], hv.y, accn);
            }
            ar += hsum2(accr);
            az += hsum2(accz);
            const float hn = bhn0 + hsum2(accn);

            const float r = sig_ap(ar);
            const float z = sig_ap(az);
            const float n = tanh_ap(fmaf(r, hn, xn));
            h1s = fmaf(z, h1s - n, n);

            h1buf[wl][t][lane] = h1s;
        }
        __syncwarp();

        // =================== PHASE 2: layer 2 over the same chunk ==========
        // W[0..15]=xr, [16..31]=xz, [32..47]=xn, [48..63]=hr, [64..79]=hz, [80..95]=hn
        {
            const ull* p0 = reinterpret_cast<const ull*>(Wih1 + (lane)      * HID);
            const ull* p1 = reinterpret_cast<const ull*>(Wih1 + (32 + lane) * HID);
            const ull* p2 = reinterpret_cast<const ull*>(Wih1 + (64 + lane) * HID);
            const ull* p3 = reinterpret_cast<const ull*>(Whh1 + (lane)      * HID);
            const ull* p4 = reinterpret_cast<const ull*>(Whh1 + (32 + lane) * HID);
            const ull* p5 = reinterpret_cast<const ull*>(Whh1 + (64 + lane) * HID);
#pragma unroll
            for (int k = 0; k < 16; k++) {
                W[k]      = p0[k]; W[16 + k] = p1[k]; W[32 + k] = p2[k];
                W[48 + k] = p3[k]; W[64 + k] = p4[k]; W[80 + k] = p5[k];
            }
        }

#pragma unroll 2
        for (int t = 0; t < CHUNK; t++) {
            hbuf[wl][t & 1][lane] = h2s;
            __syncwarp();
            const ulonglong2* xp =
                reinterpret_cast<const ulonglong2*>(&h1buf[wl][t][0]);
            const ulonglong2* hp =
                reinterpret_cast<const ulonglong2*>(&hbuf[wl][t & 1][0]);

            ull a_r = 0ull, a_z = 0ull, a_xn = 0ull, a_hn = 0ull;
#pragma unroll
            for (int k = 0; k < 8; k++) {
                const ulonglong2 xv = xp[k];
                const ulonglong2 hv = hp[k];
                a_r  = ffma2(W[2 * k],          xv.x, a_r);
                a_z  = ffma2(W[16 + 2 * k],     xv.x, a_z);
                a_xn = ffma2(W[32 + 2 * k],     xv.x, a_xn);
                a_r  = ffma2(W[48 + 2 * k],     hv.x, a_r);
                a_z  = ffma2(W[64 + 2 * k],     hv.x, a_z);
                a_hn = ffma2(W[80 + 2 * k],     hv.x, a_hn);
                a_r  = ffma2(W[2 * k + 1],      xv.y, a_r);
                a_z  = ffma2(W[16 + 2 * k + 1], xv.y, a_z);
                a_xn = ffma2(W[32 + 2 * k + 1], xv.y, a_xn);
                a_r  = ffma2(W[48 + 2 * k + 1], hv.y, a_r);
                a_z  = ffma2(W[64 + 2 * k + 1], hv.y, a_z);
                a_hn = ffma2(W[80 + 2 * k + 1], hv.y, a_hn);
            }
            const float ar = br1  + hsum2(a_r);
            const float az = bz1  + hsum2(a_z);
            const float xn = bin1 + hsum2(a_xn);
            const float hn = bhn1 + hsum2(a_hn);

            const float r = sig_ap(ar);
            const float z = sig_ap(az);
            const float n = tanh_ap(fmaf(r, hn, xn));
            h2s = fmaf(z, h2s - n, n);
        }
        __syncwarp();
    }

    // ======================= FC2 + FC epilogue =============================
    {
        hbuf[wl][0][lane] = h2s;
        __syncwarp();
        const ulonglong2* hp = reinterpret_cast<const ulonglong2*>(&hbuf[wl][0][0]);
        const ull* wf = reinterpret_cast<const ull*>(Wfc2 + lane * HID);
        ull acc = 0ull;
#pragma unroll
        for (int k = 0; k < 8; k++) {
            const ulonglong2 hv = hp[k];
            acc = ffma2(wf[2 * k],     hv.x, acc);
            acc = ffma2(wf[2 * k + 1], hv.y, acc);
        }
        const float o = __ldg(bfc2 + lane) + hsum2(acc);

        float p = __ldg(Wfc + lane) * o;
#pragma unroll
        for (int off = 16; off > 0; off >>= 1)
            p += __shfl_xor_sync(0xffffffffu, p, off);
        if (lane == 0) out[warp] = p + __ldg(bfc);
    }
}

// ---------------------------------------------------------------------------
// Launch
// ---------------------------------------------------------------------------
extern "C" void kernel_launch(void* const* d_in, const int* in_sizes, int n_in,
                              void* d_out, int out_size)
{
    const float* x     = (const float*)d_in[0];
    const float* Wih0  = (const float*)d_in[1];
    const float* Whh0  = (const float*)d_in[2];
    const float* bih0  = (const float*)d_in[3];
    const float* bhh0  = (const float*)d_in[4];
    const float* Wih1  = (const float*)d_in[5];
    const float* Whh1  = (const float*)d_in[6];
    const float* bih1  = (const float*)d_in[7];
    const float* bhh1  = (const float*)d_in[8];
    const float* Wfc2  = (const float*)d_in[9];
    const float* bfc2  = (const float*)d_in[10];
    const float* Wfc   = (const float*)d_in[11];
    const float* bfc   = (const float*)d_in[12];
    float* out = (float*)d_out;

    const int threads = 128;                      // 4 warps = 4 rows per CTA
    const int blocks  = B_ROWS / 4;               // 1024 CTAs

    gru_fused_kernel<<<blocks, threads>>>(x, Wih0, Whh0, bih0, bhh0,
                                          Wih1, Whh1, bih1, bhh1,
                                          Wfc2, bfc2, Wfc, bfc, out);
}

// round 11
// speedup vs baseline: 1.7607x; 1.7607x over previous
#include <cuda_runtime.h>
#include <cuda_bf16.h>
#include <cstdint>

// ---------------------------------------------------------------------------
// 2-layer GRU (H=32, INPUT=4, B=4096, S=512) + FC(32->32) + FC(32->1)
//
// R6 two-kernel structure, but each warp now processes TWO batch rows:
// weights (the register-pressure limiter) are shared across rows, doubling
// FMA work and ILP per warp at nearly constant register cost, and halving
// the number of warps (3.46 -> 1.73 waves in pass 2).
// ---------------------------------------------------------------------------

#define B_ROWS 4096
#define SEQ    512
#define HID    32
#define RING   8
#define NWARP  (B_ROWS / 2)   // 2048 warps, 2 rows each

typedef unsigned long long ull;

__device__ float g_h1[(size_t)B_ROWS * SEQ * HID];   // 268 MB scratch

__device__ __forceinline__ ull ffma2(ull a, ull b, ull c) {
    ull d;
    asm("fma.rn.f32x2 %0, %1, %2, %3;" : "=l"(d) : "l"(a), "l"(b), "l"(c));
    return d;
}
__device__ __forceinline__ float hsum2(ull v) {
    float2 r;
    asm("mov.b64 {%0, %1}, %2;" : "=f"(r.x), "=f"(r.y) : "l"(v));
    return r.x + r.y;
}
__device__ __forceinline__ float tanh_ap(float x) {
    float y;
    asm("tanh.approx.f32 %0, %1;" : "=f"(y) : "f"(x));
    return y;
}
__device__ __forceinline__ float sig_ap(float x) {
    return fmaf(0.5f, tanh_ap(0.5f * x), 0.5f);
}
__device__ __forceinline__ void cp_async4(uint32_t smem_addr, const float* gptr) {
    asm volatile("cp.async.ca.shared.global [%0], [%1], 4;"
                 :: "r"(smem_addr), "l"(gptr));
}
__device__ __forceinline__ void cp_commit() {
    asm volatile("cp.async.commit_group;");
}
__device__ __forceinline__ void cp_wait_ring() {
    asm volatile("cp.async.wait_group %0;" :: "n"(RING - 1));
}

// ---------------------------------------------------------------------------
// Pass 1: GRU layer 1, 2 rows/warp.  x:[B,S,4] -> h1:[B,S,32]
// ---------------------------------------------------------------------------
__global__ __launch_bounds__(128, 3)
void gru_layer1_kernel(const float* __restrict__ x,
                       const float* __restrict__ Wih,   // [96,4]
                       const float* __restrict__ Whh,   // [96,32]
                       const float* __restrict__ bih,   // [96]
                       const float* __restrict__ bhh)   // [96]
{
    __shared__ __align__(16) float hbuf[4][2][2][HID];     // [warp][buf][row][unit]
    __shared__ __align__(16) float xring[4][RING][2][4];   // 32B per slot

    const int warp = (blockIdx.x * blockDim.x + threadIdx.x) >> 5;
    const int wl   = threadIdx.x >> 5;
    const int lane = threadIdx.x & 31;
    if (warp >= NWARP) return;

    ull whr[16], whz[16], whn[16];
    {
        const ull* pr = reinterpret_cast<const ull*>(Whh + (lane)      * HID);
        const ull* pz = reinterpret_cast<const ull*>(Whh + (32 + lane) * HID);
        const ull* pn = reinterpret_cast<const ull*>(Whh + (64 + lane) * HID);
#pragma unroll
        for (int k = 0; k < 16; k++) { whr[k] = pr[k]; whz[k] = pz[k]; whn[k] = pn[k]; }
    }
    const float4 wir = reinterpret_cast<const float4*>(Wih)[lane];
    const float4 wiz = reinterpret_cast<const float4*>(Wih)[32 + lane];
    const float4 win = reinterpret_cast<const float4*>(Wih)[64 + lane];

    const float br  = bih[lane]      + bhh[lane];
    const float bz  = bih[32 + lane] + bhh[32 + lane];
    const float bin = bih[64 + lane];
    const float bhn = bhh[64 + lane];

    const int r0 = warp * 2, r1 = warp * 2 + 1;
    const float* xs0 = x + (size_t)r0 * SEQ * 4;
    const float* xs1 = x + (size_t)r1 * SEQ * 4;
    float* op0 = g_h1 + (size_t)r0 * SEQ * HID + lane;
    float* op1 = g_h1 + (size_t)r1 * SEQ * HID + lane;

    const uint32_t ring_base =
        (uint32_t)__cvta_generic_to_shared(&xring[wl][0][0][0]);

    // lanes 0-3 feed row0's 4 words, lanes 4-7 feed row1's
    const bool ld_act = lane < 8;
    const float* xg = (lane < 4) ? (xs0 + lane) : (xs1 + (lane - 4));

#pragma unroll
    for (int d = 0; d < RING; d++) {
        if (ld_act) cp_async4(ring_base + d * 32 + lane * 4, xg + d * 4);
        cp_commit();
    }

    float h0 = 0.0f, h1 = 0.0f;
#pragma unroll 1
    for (int s = 0; s < SEQ; s++) {
        hbuf[wl][s & 1][0][lane] = h0;
        hbuf[wl][s & 1][1][lane] = h1;
        cp_wait_ring();
        __syncwarp();

        const float4 xv0 =
            *reinterpret_cast<const float4*>(&xring[wl][s & (RING - 1)][0][0]);
        const float4 xv1 =
            *reinterpret_cast<const float4*>(&xring[wl][s & (RING - 1)][1][0]);
        const ulonglong2* hp0 =
            reinterpret_cast<const ulonglong2*>(&hbuf[wl][s & 1][0][0]);
        const ulonglong2* hp1 =
            reinterpret_cast<const ulonglong2*>(&hbuf[wl][s & 1][1][0]);

        if (ld_act && s + RING < SEQ)
            cp_async4(ring_base + ((s + RING) & (RING - 1)) * 32 + lane * 4,
                      xg + (s + RING) * 4);
        cp_commit();

        float ar0 = br, az0 = bz, xn0 = bin;
        float ar1 = br, az1 = bz, xn1 = bin;
        ar0 = fmaf(wir.x, xv0.x, ar0); ar0 = fmaf(wir.y, xv0.y, ar0);
        ar0 = fmaf(wir.z, xv0.z, ar0); ar0 = fmaf(wir.w, xv0.w, ar0);
        az0 = fmaf(wiz.x, xv0.x, az0); az0 = fmaf(wiz.y, xv0.y, az0);
        az0 = fmaf(wiz.z, xv0.z, az0); az0 = fmaf(wiz.w, xv0.w, az0);
        xn0 = fmaf(win.x, xv0.x, xn0); xn0 = fmaf(win.y, xv0.y, xn0);
        xn0 = fmaf(win.z, xv0.z, xn0); xn0 = fmaf(win.w, xv0.w, xn0);
        ar1 = fmaf(wir.x, xv1.x, ar1); ar1 = fmaf(wir.y, xv1.y, ar1);
        ar1 = fmaf(wir.z, xv1.z, ar1); ar1 = fmaf(wir.w, xv1.w, ar1);
        az1 = fmaf(wiz.x, xv1.x, az1); az1 = fmaf(wiz.y, xv1.y, az1);
        az1 = fmaf(wiz.z, xv1.z, az1); az1 = fmaf(wiz.w, xv1.w, az1);
        xn1 = fmaf(win.x, xv1.x, xn1); xn1 = fmaf(win.y, xv1.y, xn1);
        xn1 = fmaf(win.z, xv1.z, xn1); xn1 = fmaf(win.w, xv1.w, xn1);

        ull ra0 = 0ull, za0 = 0ull, na0 = 0ull;
        ull ra1 = 0ull, za1 = 0ull, na1 = 0ull;
#pragma unroll
        for (int k = 0; k < 8; k++) {
            const ulonglong2 hv0 = hp0[k];
            const ulonglong2 hv1 = hp1[k];
            ra0 = ffma2(whr[2 * k],     hv0.x, ra0);
            za0 = ffma2(whz[2 * k],     hv0.x, za0);
            na0 = ffma2(whn[2 * k],     hv0.x, na0);
            ra1 = ffma2(whr[2 * k],     hv1.x, ra1);
            za1 = ffma2(whz[2 * k],     hv1.x, za1);
            na1 = ffma2(whn[2 * k],     hv1.x, na1);
            ra0 = ffma2(whr[2 * k + 1], hv0.y, ra0);
            za0 = ffma2(whz[2 * k + 1], hv0.y, za0);
            na0 = ffma2(whn[2 * k + 1], hv0.y, na0);
            ra1 = ffma2(whr[2 * k + 1], hv1.y, ra1);
            za1 = ffma2(whz[2 * k + 1], hv1.y, za1);
            na1 = ffma2(whn[2 * k + 1], hv1.y, na1);
        }
        ar0 += hsum2(ra0);  az0 += hsum2(za0);
        ar1 += hsum2(ra1);  az1 += hsum2(za1);
        const float hn0 = bhn + hsum2(na0);
        const float hn1 = bhn + hsum2(na1);

        const float rr0 = sig_ap(ar0);
        const float zz0 = sig_ap(az0);
        const float nn0 = tanh_ap(fmaf(rr0, hn0, xn0));
        h0 = fmaf(zz0, h0 - nn0, nn0);
        const float rr1 = sig_ap(ar1);
        const float zz1 = sig_ap(az1);
        const float nn1 = tanh_ap(fmaf(rr1, hn1, xn1));
        h1 = fmaf(zz1, h1 - nn1, nn1);

        op0[(size_t)s * HID] = h0;
        op1[(size_t)s * HID] = h1;
    }
}

// ---------------------------------------------------------------------------
// Pass 2: GRU layer 2 + FC, 2 rows/warp.  h1:[B,S,32] -> out:[B]
// ---------------------------------------------------------------------------
__global__ __launch_bounds__(128, 2)
void gru_layer2_fc_kernel(const float* __restrict__ Wih,   // [96,32]
                          const float* __restrict__ Whh,   // [96,32]
                          const float* __restrict__ bih,   // [96]
                          const float* __restrict__ bhh,   // [96]
                          const float* __restrict__ Wfc2,  // [32,32]
                          const float* __restrict__ bfc2,  // [32]
                          const float* __restrict__ Wfc,   // [1,32]
                          const float* __restrict__ bfc,   // [1]
                          float* __restrict__ out)
{
    __shared__ __align__(16) float hbuf[4][2][2][HID];     // [warp][buf][row][unit]
    __shared__ __align__(16) float xring[4][RING][2][HID]; // 256B per slot

    const int warp = (blockIdx.x * blockDim.x + threadIdx.x) >> 5;
    const int wl   = threadIdx.x >> 5;
    const int lane = threadIdx.x & 31;
    if (warp >= NWARP) return;

    ull wir[16], wiz[16], win[16], whr[16], whz[16], whn[16];
    {
        const ull* p0 = reinterpret_cast<const ull*>(Wih + (lane)      * HID);
        const ull* p1 = reinterpret_cast<const ull*>(Wih + (32 + lane) * HID);
        const ull* p2 = reinterpret_cast<const ull*>(Wih + (64 + lane) * HID);
        const ull* p3 = reinterpret_cast<const ull*>(Whh + (lane)      * HID);
        const ull* p4 = reinterpret_cast<const ull*>(Whh + (32 + lane) * HID);
        const ull* p5 = reinterpret_cast<const ull*>(Whh + (64 + lane) * HID);
#pragma unroll
        for (int k = 0; k < 16; k++) {
            wir[k] = p0[k]; wiz[k] = p1[k]; win[k] = p2[k];
            whr[k] = p3[k]; whz[k] = p4[k]; whn[k] = p5[k];
        }
    }
    const float br  = bih[lane]      + bhh[lane];
    const float bz  = bih[32 + lane] + bhh[32 + lane];
    const float bin = bih[64 + lane];
    const float bhn = bhh[64 + lane];

    const float* xs0 = g_h1 + (size_t)(warp * 2)     * SEQ * HID;
    const float* xs1 = g_h1 + (size_t)(warp * 2 + 1) * SEQ * HID;

    const uint32_t ring_base =
        (uint32_t)__cvta_generic_to_shared(&xring[wl][0][0][0]);

#pragma unroll
    for (int d = 0; d < RING; d++) {
        cp_async4(ring_base + d * 256 + lane * 4,       xs0 + d * HID + lane);
        cp_async4(ring_base + d * 256 + 128 + lane * 4, xs1 + d * HID + lane);
        cp_commit();
    }

    float h0 = 0.0f, h1 = 0.0f;
#pragma unroll 1
    for (int s = 0; s < SEQ; s++) {
        hbuf[wl][s & 1][0][lane] = h0;
        hbuf[wl][s & 1][1][lane] = h1;
        cp_wait_ring();
        __syncwarp();

        const ulonglong2* xp0 =
            reinterpret_cast<const ulonglong2*>(&xring[wl][s & (RING - 1)][0][0]);
        const ulonglong2* xp1 =
            reinterpret_cast<const ulonglong2*>(&xring[wl][s & (RING - 1)][1][0]);
        const ulonglong2* hp0 =
            reinterpret_cast<const ulonglong2*>(&hbuf[wl][s & 1][0][0]);
        const ulonglong2* hp1 =
            reinterpret_cast<const ulonglong2*>(&hbuf[wl][s & 1][1][0]);

        if (s + RING < SEQ) {
            const uint32_t rb = ring_base + ((s + RING) & (RING - 1)) * 256;
            cp_async4(rb + lane * 4,       xs0 + (s + RING) * HID + lane);
            cp_async4(rb + 128 + lane * 4, xs1 + (s + RING) * HID + lane);
        }
        cp_commit();

        ull r0a = 0ull, z0a = 0ull, x0a = 0ull, n0a = 0ull;
        ull r1a = 0ull, z1a = 0ull, x1a = 0ull, n1a = 0ull;
#pragma unroll
        for (int k = 0; k < 8; k++) {
            const ulonglong2 xv0 = xp0[k];
            const ulonglong2 hv0 = hp0[k];
            const ulonglong2 xv1 = xp1[k];
            const ulonglong2 hv1 = hp1[k];
            r0a = ffma2(wir[2 * k],     xv0.x, r0a);
            z0a = ffma2(wiz[2 * k],     xv0.x, z0a);
            x0a = ffma2(win[2 * k],     xv0.x, x0a);
            r0a = ffma2(whr[2 * k],     hv0.x, r0a);
            z0a = ffma2(whz[2 * k],     hv0.x, z0a);
            n0a = ffma2(whn[2 * k],     hv0.x, n0a);
            r1a = ffma2(wir[2 * k],     xv1.x, r1a);
            z1a = ffma2(wiz[2 * k],     xv1.x, z1a);
            x1a = ffma2(win[2 * k],     xv1.x, x1a);
            r1a = ffma2(whr[2 * k],     hv1.x, r1a);
            z1a = ffma2(whz[2 * k],     hv1.x, z1a);
            n1a = ffma2(whn[2 * k],     hv1.x, n1a);
            r0a = ffma2(wir[2 * k + 1], xv0.y, r0a);
            z0a = ffma2(wiz[2 * k + 1], xv0.y, z0a);
            x0a = ffma2(win[2 * k + 1], xv0.y, x0a);
            r0a = ffma2(whr[2 * k + 1], hv0.y, r0a);
            z0a = ffma2(whz[2 * k + 1], hv0.y, z0a);
            n0a = ffma2(whn[2 * k + 1], hv0.y, n0a);
            r1a = ffma2(wir[2 * k + 1], xv1.y, r1a);
            z1a = ffma2(wiz[2 * k + 1], xv1.y, z1a);
            x1a = ffma2(win[2 * k + 1], xv1.y, x1a);
            r1a = ffma2(whr[2 * k + 1], hv1.y, r1a);
            z1a = ffma2(whz[2 * k + 1], hv1.y, z1a);
            n1a = ffma2(whn[2 * k + 1], hv1.y, n1a);
        }
        const float ar0 = br  + hsum2(r0a);
        const float az0 = bz  + hsum2(z0a);
        const float xn0 = bin + hsum2(x0a);
        const float hn0 = bhn + hsum2(n0a);
        const float ar1 = br  + hsum2(r1a);
        const float az1 = bz  + hsum2(z1a);
        const float xn1 = bin + hsum2(x1a);
        const float hn1 = bhn + hsum2(n1a);

        const float rr0 = sig_ap(ar0);
        const float zz0 = sig_ap(az0);
        const float nn0 = tanh_ap(fmaf(rr0, hn0, xn0));
        h0 = fmaf(zz0, h0 - nn0, nn0);
        const float rr1 = sig_ap(ar1);
        const float zz1 = sig_ap(az1);
        const float nn1 = tanh_ap(fmaf(rr1, hn1, xn1));
        h1 = fmaf(zz1, h1 - nn1, nn1);
    }

    // FC2 + FC epilogue for both rows
    {
        hbuf[wl][0][0][lane] = h0;
        hbuf[wl][0][1][lane] = h1;
        __syncwarp();
        const ulonglong2* hp0 =
            reinterpret_cast<const ulonglong2*>(&hbuf[wl][0][0][0]);
        const ulonglong2* hp1 =
            reinterpret_cast<const ulonglong2*>(&hbuf[wl][0][1][0]);
        const ull* wf = reinterpret_cast<const ull*>(Wfc2 + lane * HID);
        ull a0 = 0ull, a1 = 0ull;
#pragma unroll
        for (int k = 0; k < 8; k++) {
            const ulonglong2 hv0 = hp0[k];
            const ulonglong2 hv1 = hp1[k];
            a0 = ffma2(wf[2 * k],     hv0.x, a0);
            a1 = ffma2(wf[2 * k],     hv1.x, a1);
            a0 = ffma2(wf[2 * k + 1], hv0.y, a0);
            a1 = ffma2(wf[2 * k + 1], hv1.y, a1);
        }
        const float bf2 = __ldg(bfc2 + lane);
        const float o0 = bf2 + hsum2(a0);
        const float o1 = bf2 + hsum2(a1);

        const float wfc = __ldg(Wfc + lane);
        float p0 = wfc * o0;
        float p1 = wfc * o1;
#pragma unroll
        for (int off = 16; off > 0; off >>= 1) {
            p0 += __shfl_xor_sync(0xffffffffu, p0, off);
            p1 += __shfl_xor_sync(0xffffffffu, p1, off);
        }
        if (lane == 0) {
            const float bb = __ldg(bfc);
            out[warp * 2]     = p0 + bb;
            out[warp * 2 + 1] = p1 + bb;
        }
    }
}

// ---------------------------------------------------------------------------
// Launch
// ---------------------------------------------------------------------------
extern "C" void kernel_launch(void* const* d_in, const int* in_sizes, int n_in,
                              void* d_out, int out_size)
{
    const float* x     = (const float*)d_in[0];
    const float* Wih0  = (const float*)d_in[1];
    const float* Whh0  = (const float*)d_in[2];
    const float* bih0  = (const float*)d_in[3];
    const float* bhh0  = (const float*)d_in[4];
    const float* Wih1  = (const float*)d_in[5];
    const float* Whh1  = (const float*)d_in[6];
    const float* bih1  = (const float*)d_in[7];
    const float* bhh1  = (const float*)d_in[8];
    const float* Wfc2  = (const float*)d_in[9];
    const float* bfc2  = (const float*)d_in[10];
    const float* Wfc   = (const float*)d_in[11];
    const float* bfc   = (const float*)d_in[12];
    float* out = (float*)d_out;

    const int threads = 128;                 // 4 warps = 8 rows per CTA
    const int blocks  = NWARP / 4;           // 512 CTAs

    gru_layer1_kernel<<<blocks, threads>>>(x, Wih0, Whh0, bih0, bhh0);
    gru_layer2_fc_kernel<<<blocks, threads>>>(Wih1, Whh1, bih1, bhh1,
                                              Wfc2, bfc2, Wfc, bfc, out);
}